// round 16
// baseline (speedup 1.0000x reference)
#include <cuda_runtime.h>
#include <cuda_fp16.h>
#include <stdint.h>
#include <math.h>

// ---------------- problem constants ----------------
#define B_  32
#define S_  4096
#define D_  512
#define H_  512
#define M_  (B_ * S_)

#define SPLIT 32
#define S_PER_SPLIT 128

// gemm_e tiling (R10 skeleton, KCH=256: 16 stages)
#define MT   64            // M rows per CTA
#define NCH  64            // N chunk
#define KCH  256           // K chunk (B staging)
#define NSTG 16            // (512/NCH) * (512/KCH)
#define APITCH 1040u       // A row pitch bytes (512 fp16 = 1024B + 16 pad)
#define BPITCH 528u        // B row pitch bytes (256 fp16 = 512B + 16 pad)
#define A_OFF   0u
#define B_OFF   66560u           // 64*1040
#define B_STG   33792u           // 64*528 per stage buffer
#define T_OFF   134144u          // B_OFF + 2*B_STG
#define V_OFF   136192u
#define E_OFF   138240u
#define SMEM_TOTAL 139264

// ---------------- device scratch ----------------
__device__ float g_t[B_ * H_];
__device__ float g_e[B_ * S_];
__device__ float g_ctx[B_ * SPLIT * D_];
__device__ __half g_wsh[H_ * D_];   // Ws fp16 (row h, k contiguous)

// ---------------- helpers ----------------
__device__ __forceinline__ uint32_t smem_u32(const void* p) {
    uint32_t a;
    asm("{ .reg .u64 t; cvta.to.shared.u64 t, %1; cvt.u32.u64 %0, t; }" : "=r"(a) : "l"(p));
    return a;
}
__device__ __forceinline__ uint32_t pack_h2(float a, float b) {
    __half2 h = __floats2half2_rn(a, b);
    return *(uint32_t*)&h;
}
__device__ __forceinline__ void cp16(uint32_t dst, const void* src) {
    asm volatile("cp.async.cg.shared.global [%0], [%1], 16;" :: "r"(dst), "l"(src));
}
#define CP_COMMIT() asm volatile("cp.async.commit_group;" ::: "memory")
#define CP_WAIT(n)  asm volatile("cp.async.wait_group %0;" :: "n"(n) : "memory")

#define LDSM4(r0, r1, r2, r3, addr) \
    asm volatile("ldmatrix.sync.aligned.m8n8.x4.shared.b16 {%0,%1,%2,%3}, [%4];" \
                 : "=r"(r0), "=r"(r1), "=r"(r2), "=r"(r3) : "r"(addr))

#define MMAH16816(c0, c1, c2, c3, a0, a1, a2, a3, b0, b1) \
    asm volatile("mma.sync.aligned.m16n8k16.row.col.f32.f16.f16.f32 " \
                 "{%0,%1,%2,%3}, {%4,%5,%6,%7}, {%8,%9}, {%0,%1,%2,%3};" \
                 : "+f"(c0), "+f"(c1), "+f"(c2), "+f"(c3) \
                 : "r"(a0), "r"(a1), "r"(a2), "r"(a3), "r"(b0), "r"(b1))

// ---------------- K0: convert Ws to fp16 ----------------
__global__ __launch_bounds__(256) void wsplit_kernel(const float* __restrict__ W) {
    int idx = blockIdx.x * 256 + threadIdx.x;
    int h = idx >> 9, d = idx & 511;
    float w = W[h * (2 * D_) + D_ + d];
    g_wsh[idx] = __float2half_rn(w);
}

// ---------------- K1: t[b,h] = targ[b,:] . W[h,:D] (fp32) ----------------
__global__ __launch_bounds__(512) void t_kernel(const float* __restrict__ targ,
                                                const float* __restrict__ W) {
    __shared__ float ts[D_];
    int b = blockIdx.x, h = threadIdx.x;
    ts[h] = targ[b * D_ + h];
    __syncthreads();
    const float* wr = W + (size_t)h * (2 * D_);
    float s = 0.0f;
#pragma unroll 8
    for (int d = 0; d < D_; d += 4) {
        float4 w4 = *(const float4*)(wr + d);
        s += ts[d] * w4.x + ts[d + 1] * w4.y + ts[d + 2] * w4.z + ts[d + 3] * w4.w;
    }
    g_t[b * H_ + h] = s;
}

// ---------------- K2: fp16 1-plane mma GEMM + tanh + V-dot ----------------
__global__ __launch_bounds__(256, 1) void gemm_e_mma(const float* __restrict__ src,
                                                     const float* __restrict__ V) {
    extern __shared__ __align__(1024) char smem[];
    const int tid = threadIdx.x;
    const int lane = tid & 31;
    const int wid = tid >> 5;
    const int m_base = blockIdx.x * MT;
    const int b = blockIdx.x >> 6;                 // 64 CTAs per batch

    float* ts = (float*)(smem + T_OFF);
    float* vs = (float*)(smem + V_OFF);
    float* e_sm = (float*)(smem + E_OFF);
    const uint32_t sb = smem_u32(smem);

    for (int i = tid; i < 512; i += 256) {
        ts[i] = g_t[b * H_ + i];
        vs[i] = V[i];
    }

    const char* GHB = (const char*)g_wsh;

    // ---- issue B stage 0 (nc=0, ks=0): 2048 x 16B ----
    {
        const uint32_t d0 = sb + B_OFF;
#pragma unroll
        for (int r = 0; r < 8; ++r) {
            int i = tid + r * 256;                 // 0..2047
            int n = i >> 5, c8 = i & 31;           // row 0..63, 32 x 16B per row
            const char* srcp = GHB + (size_t)n * 1024 + (size_t)c8 * 16;
            cp16(d0 + (uint32_t)n * BPITCH + (uint32_t)c8 * 16, srcp);
        }
        CP_COMMIT();
    }

    // ---- stage A (64 x 512 fp32 -> fp16, resident single buffer) ----
    const float* Ab = src + (size_t)m_base * D_;
    for (int i = tid; i < 8192; i += 256) {
        int row = i >> 7;
        int c4 = (i & 127) << 2;
        float4 v = *(const float4*)(Ab + (size_t)row * D_ + c4);
        uint32_t off = (uint32_t)row * APITCH + (uint32_t)c4 * 2;
        *(uint2*)(smem + A_OFF + off) = make_uint2(pack_h2(v.x, v.y), pack_h2(v.z, v.w));
    }

    const int wm = wid >> 2;                       // 0..1
    const int wn = wid & 3;                        // 0..3
    const int g = lane >> 2;
    const int c2 = (lane & 3) * 2;

    const uint32_t a_row  = (uint32_t)(wm * 32 + (lane & 15));
    const uint32_t a_koff = (uint32_t)((lane >> 4) * 8);
    const uint32_t b_row  = (uint32_t)(wn * 16 + (lane & 7) + ((lane >> 4) & 1) * 8);
    const uint32_t b_koff = (uint32_t)(((lane >> 3) & 1) * 8);

    const uint32_t a_base = sb + A_OFF + a_row * APITCH + a_koff * 2;

    float e_acc[4] = {0.f, 0.f, 0.f, 0.f};
    float accH[2][2][4];

    for (int s = 0; s < NSTG; ++s) {
        const int nc = s >> 1;
        const int ks = s & 1;
        const int buf = s & 1;

        if (s + 1 < NSTG) {
            const int nc1 = (s + 1) >> 1;
            const int ks1 = (s + 1) & 1;
            const uint32_t d1 = sb + B_OFF + (uint32_t)(buf ^ 1) * B_STG;
            const size_t gbase = (size_t)nc1 * NCH * 1024 + (size_t)ks1 * 512;
#pragma unroll
            for (int r = 0; r < 8; ++r) {
                int i = tid + r * 256;
                int n = i >> 5, c8 = i & 31;
                const char* srcp = GHB + gbase + (size_t)n * 1024 + (size_t)c8 * 16;
                cp16(d1 + (uint32_t)n * BPITCH + (uint32_t)c8 * 16, srcp);
            }
            CP_COMMIT();
            CP_WAIT(1);
        } else {
            CP_WAIT(0);
        }
        __syncthreads();

        if (ks == 0) {
#pragma unroll
            for (int i = 0; i < 2; ++i)
#pragma unroll
                for (int j = 0; j < 2; ++j)
#pragma unroll
                    for (int r = 0; r < 4; ++r) accH[i][j][r] = 0.f;
        }

        const uint32_t b_hi_base = sb + B_OFF + (uint32_t)buf * B_STG + b_row * BPITCH + b_koff * 2;
        const uint32_t a_kchunk = (uint32_t)(ks * KCH) * 2;

#pragma unroll
        for (int kk = 0; kk < 16; ++kk) {
            const uint32_t kb = (uint32_t)kk * 32;
            uint32_t a0[4], a1[4], bh[4];
            LDSM4(a0[0], a0[1], a0[2], a0[3], a_base + a_kchunk + kb);
            LDSM4(a1[0], a1[1], a1[2], a1[3], a_base + a_kchunk + kb + 16u * APITCH);
            LDSM4(bh[0], bh[1], bh[2], bh[3], b_hi_base + kb);

            MMAH16816(accH[0][0][0], accH[0][0][1], accH[0][0][2], accH[0][0][3],
                      a0[0], a0[1], a0[2], a0[3], bh[0], bh[1]);
            MMAH16816(accH[0][1][0], accH[0][1][1], accH[0][1][2], accH[0][1][3],
                      a0[0], a0[1], a0[2], a0[3], bh[2], bh[3]);
            MMAH16816(accH[1][0][0], accH[1][0][1], accH[1][0][2], accH[1][0][3],
                      a1[0], a1[1], a1[2], a1[3], bh[0], bh[1]);
            MMAH16816(accH[1][1][0], accH[1][1][1], accH[1][1][2], accH[1][1][3],
                      a1[0], a1[1], a1[2], a1[3], bh[2], bh[3]);
        }
        __syncthreads();

        if (ks == 1) {
            // epilogue for this nc: e += V * tanh(accH + t)
#pragma unroll
            for (int mt = 0; mt < 2; ++mt) {
#pragma unroll
                for (int nt = 0; nt < 2; ++nt) {
                    const int n0 = nc * NCH + wn * 16 + nt * 8 + c2;
                    const float t0 = ts[n0], t1 = ts[n0 + 1];
                    const float v0 = vs[n0], v1 = vs[n0 + 1];
#pragma unroll
                    for (int r = 0; r < 4; ++r) {
                        const float tv = (r & 1) ? t1 : t0;
                        const float vv = (r & 1) ? v1 : v0;
                        float x = accH[mt][nt][r] + tv;
                        float ex = __expf(2.0f * x);
                        float th = 1.0f - __fdividef(2.0f, ex + 1.0f);
                        e_acc[mt * 2 + (r >> 1)] = fmaf(vv, th, e_acc[mt * 2 + (r >> 1)]);
                    }
                }
            }
        }
    }

    // reduce e over the 4 lanes sharing a row
#pragma unroll
    for (int j = 0; j < 4; ++j) {
        e_acc[j] += __shfl_xor_sync(0xffffffffu, e_acc[j], 1);
        e_acc[j] += __shfl_xor_sync(0xffffffffu, e_acc[j], 2);
    }
    if ((lane & 3) == 0) {
#pragma unroll
        for (int j = 0; j < 4; ++j) {
            int row = wm * 32 + (j >> 1) * 16 + (j & 1) * 8 + g;
            e_sm[wn * 64 + row] = e_acc[j];
        }
    }
    __syncthreads();
    if (tid < MT) {
        float s = e_sm[tid] + e_sm[64 + tid] + e_sm[128 + tid] + e_sm[192 + tid];
        g_e[m_base + tid] = s;
    }
}

// ---------------- K3: softmax (1024 threads) ----------------
__global__ __launch_bounds__(1024) void softmax_kernel(const float* __restrict__ mask,
                                                       float* __restrict__ out_att) {
    const int b = blockIdx.x;
    const int tid = threadIdx.x;
    const float* e = g_e + (size_t)b * S_;
    __shared__ float red[32];

    float vals[4];
    float mx = -1e30f;
#pragma unroll
    for (int i = 0; i < 4; ++i) {
        vals[i] = e[tid + i * 1024];
        mx = fmaxf(mx, vals[i]);
    }
#pragma unroll
    for (int o = 16; o >= 1; o >>= 1) mx = fmaxf(mx, __shfl_xor_sync(0xffffffffu, mx, o));
    if ((tid & 31) == 0) red[tid >> 5] = mx;
    __syncthreads();
    float M = red[0];
#pragma unroll
    for (int i = 1; i < 32; ++i) M = fmaxf(M, red[i]);
    __syncthreads();

    float sum = 0.0f;
#pragma unroll
    for (int i = 0; i < 4; ++i) {
        vals[i] = expf(vals[i] - M);
        sum += vals[i];
    }
#pragma unroll
    for (int o = 16; o >= 1; o >>= 1) sum += __shfl_xor_sync(0xffffffffu, sum, o);
    if ((tid & 31) == 0) red[tid >> 5] = sum;
    __syncthreads();
    float Ssum = 0.0f;
#pragma unroll
    for (int i = 0; i < 32; ++i) Ssum += red[i];

    const float inv = 1.0f / Ssum;
    const float* mrow = mask + (size_t)b * S_;
    float* orow = out_att + (size_t)b * S_;
#pragma unroll
    for (int i = 0; i < 4; ++i) {
        int s = tid + i * 1024;
        orow[s] = vals[i] * inv * mrow[s];
    }
}

// ---------------- K4: ctx partials ----------------
__global__ __launch_bounds__(512) void ctx_partial_kernel(const float* __restrict__ src,
                                                          const float* __restrict__ att) {
    __shared__ float aw[S_PER_SPLIT];
    const int b = blockIdx.x;
    const int sp = blockIdx.y;
    const int tid = threadIdx.x;
    if (tid < S_PER_SPLIT) aw[tid] = att[(size_t)b * S_ + sp * S_PER_SPLIT + tid];
    __syncthreads();

    const float* p = src + ((size_t)b * S_ + (size_t)sp * S_PER_SPLIT) * D_ + tid;
    float a0 = 0.f, a1 = 0.f, a2 = 0.f, a3 = 0.f;
#pragma unroll 4
    for (int s = 0; s < S_PER_SPLIT; s += 4) {
        a0 = fmaf(aw[s + 0], p[(size_t)(s + 0) * D_], a0);
        a1 = fmaf(aw[s + 1], p[(size_t)(s + 1) * D_], a1);
        a2 = fmaf(aw[s + 2], p[(size_t)(s + 2) * D_], a2);
        a3 = fmaf(aw[s + 3], p[(size_t)(s + 3) * D_], a3);
    }
    g_ctx[((size_t)b * SPLIT + sp) * D_ + tid] = (a0 + a1) + (a2 + a3);
}

// ---------------- K5: reduce + residual ----------------
__global__ __launch_bounds__(512) void reduce_kernel(const float* __restrict__ targ,
                                                     float* __restrict__ out_hidden) {
    const int b = blockIdx.x;
    const int d = threadIdx.x;
    float s = targ[b * D_ + d];
#pragma unroll
    for (int sp = 0; sp < SPLIT; ++sp) s += g_ctx[((size_t)b * SPLIT + sp) * D_ + d];
    out_hidden[b * D_ + d] = s;
}

// ---------------- launcher ----------------
extern "C" void kernel_launch(void* const* d_in, const int* in_sizes, int n_in,
                              void* d_out, int out_size) {
    const float* targ = (const float*)d_in[0];
    const float* src  = (const float*)d_in[1];
    const float* mask = (const float*)d_in[2];
    const float* W    = (const float*)d_in[3];
    const float* V    = (const float*)d_in[4];

    float* out = (float*)d_out;
    float* out_att    = out;
    float* out_hidden = out + B_ * S_;

    cudaFuncSetAttribute(gemm_e_mma, cudaFuncAttributeMaxDynamicSharedMemorySize, SMEM_TOTAL);

    wsplit_kernel<<<H_ * D_ / 256, 256>>>(W);
    t_kernel<<<B_, D_>>>(targ, W);
    gemm_e_mma<<<M_ / MT, 256, SMEM_TOTAL>>>(src, V);
    softmax_kernel<<<B_, 1024>>>(mask, out_att);
    dim3 g4(B_, SPLIT);
    ctx_partial_kernel<<<g4, D_>>>(src, out_att);
    reduce_kernel<<<B_, D_>>>(targ, out_hidden);
}

// round 17
// speedup vs baseline: 1.2647x; 1.2647x over previous
#include <cuda_runtime.h>
#include <cuda_fp16.h>
#include <stdint.h>
#include <math.h>

// ---------------- problem constants ----------------
#define B_  32
#define S_  4096
#define D_  512
#define H_  512
#define M_  (B_ * S_)

#define SPLIT 32
#define S_PER_SPLIT 128

// gemm_e tiling (R10 frozen skeleton)
#define MT   64            // M rows per CTA
#define NCH  64            // N chunk
#define KCH  128           // K chunk (B staging)
#define NSTG 32            // (512/NCH) * (512/KCH)
#define APITCH 1040u       // A row pitch bytes (512 fp16 = 1024B + 16 pad)
#define BPITCH 272u        // B row pitch bytes (128 fp16 = 256B + 16 pad)
#define A_OFF   0u
#define B_OFF   66560u           // 64*1040
#define B_STG   17408u           // 64*272, hi plane only
#define T_OFF   101376u          // B_OFF + 2*B_STG
#define V_OFF   103424u
#define E_OFF   105472u
#define SMEM_TOTAL 106496

// ---------------- device scratch ----------------
__device__ float g_t[B_ * H_];
__device__ float g_e[B_ * S_];
__device__ float g_ctx[B_ * SPLIT * D_];
__device__ __half g_wsh[H_ * D_];   // Ws fp16 (row h, k contiguous)

// ---------------- helpers ----------------
__device__ __forceinline__ uint32_t smem_u32(const void* p) {
    uint32_t a;
    asm("{ .reg .u64 t; cvta.to.shared.u64 t, %1; cvt.u32.u64 %0, t; }" : "=r"(a) : "l"(p));
    return a;
}
__device__ __forceinline__ uint32_t pack_h2(float a, float b) {
    __half2 h = __floats2half2_rn(a, b);
    return *(uint32_t*)&h;
}
__device__ __forceinline__ void cp16(uint32_t dst, const void* src) {
    asm volatile("cp.async.cg.shared.global [%0], [%1], 16;" :: "r"(dst), "l"(src));
}
#define CP_COMMIT() asm volatile("cp.async.commit_group;" ::: "memory")
#define CP_WAIT(n)  asm volatile("cp.async.wait_group %0;" :: "n"(n) : "memory")

#define LDSM4(r0, r1, r2, r3, addr) \
    asm volatile("ldmatrix.sync.aligned.m8n8.x4.shared.b16 {%0,%1,%2,%3}, [%4];" \
                 : "=r"(r0), "=r"(r1), "=r"(r2), "=r"(r3) : "r"(addr))

#define MMAH16816(c0, c1, c2, c3, a0, a1, a2, a3, b0, b1) \
    asm volatile("mma.sync.aligned.m16n8k16.row.col.f32.f16.f16.f32 " \
                 "{%0,%1,%2,%3}, {%4,%5,%6,%7}, {%8,%9}, {%0,%1,%2,%3};" \
                 : "+f"(c0), "+f"(c1), "+f"(c2), "+f"(c3) \
                 : "r"(a0), "r"(a1), "r"(a2), "r"(a3), "r"(b0), "r"(b1))

// ---------------- K0: convert Ws to fp16 ----------------
__global__ __launch_bounds__(256) void wsplit_kernel(const float* __restrict__ W) {
    int idx = blockIdx.x * 256 + threadIdx.x;
    int h = idx >> 9, d = idx & 511;
    float w = W[h * (2 * D_) + D_ + d];
    g_wsh[idx] = __float2half_rn(w);
}

// ---------------- K1: t[b,h] = targ[b,:] . W[h,:D] (fp32) ----------------
__global__ __launch_bounds__(512) void t_kernel(const float* __restrict__ targ,
                                                const float* __restrict__ W) {
    __shared__ float ts[D_];
    int b = blockIdx.x, h = threadIdx.x;
    ts[h] = targ[b * D_ + h];
    __syncthreads();
    const float* wr = W + (size_t)h * (2 * D_);
    float s = 0.0f;
#pragma unroll 8
    for (int d = 0; d < D_; d += 4) {
        float4 w4 = *(const float4*)(wr + d);
        s += ts[d] * w4.x + ts[d + 1] * w4.y + ts[d + 2] * w4.z + ts[d + 3] * w4.w;
    }
    g_t[b * H_ + h] = s;
}

// ---------------- K2: fp16 1-plane mma GEMM + tanh + V-dot (R10) ----------
__global__ __launch_bounds__(256, 1) void gemm_e_mma(const float* __restrict__ src,
                                                     const float* __restrict__ V) {
    extern __shared__ __align__(1024) char smem[];
    const int tid = threadIdx.x;
    const int lane = tid & 31;
    const int wid = tid >> 5;
    const int m_base = blockIdx.x * MT;
    const int b = blockIdx.x >> 6;                 // 64 CTAs per batch

    float* ts = (float*)(smem + T_OFF);
    float* vs = (float*)(smem + V_OFF);
    float* e_sm = (float*)(smem + E_OFF);
    const uint32_t sb = smem_u32(smem);

    for (int i = tid; i < 512; i += 256) {
        ts[i] = g_t[b * H_ + i];
        vs[i] = V[i];
    }

    const char* GHB = (const char*)g_wsh;

    // ---- issue B stage 0 (nc=0, ks=0): 1024 x 16B ----
    {
        const uint32_t d0 = sb + B_OFF;
#pragma unroll
        for (int r = 0; r < 4; ++r) {
            int i = tid + r * 256;                 // 0..1023
            int n = i >> 4, c8 = i & 15;
            const char* srcp = GHB + (size_t)n * 1024 + (size_t)c8 * 16;
            cp16(d0 + (uint32_t)n * BPITCH + (uint32_t)c8 * 16, srcp);
        }
        CP_COMMIT();
    }

    // ---- stage A (64 x 512 fp32 -> fp16, resident single buffer) ----
    const float* Ab = src + (size_t)m_base * D_;
    for (int i = tid; i < 8192; i += 256) {
        int row = i >> 7;
        int c4 = (i & 127) << 2;
        float4 v = *(const float4*)(Ab + (size_t)row * D_ + c4);
        uint32_t off = (uint32_t)row * APITCH + (uint32_t)c4 * 2;
        *(uint2*)(smem + A_OFF + off) = make_uint2(pack_h2(v.x, v.y), pack_h2(v.z, v.w));
    }

    const int wm = wid >> 2;                       // 0..1
    const int wn = wid & 3;                        // 0..3
    const int g = lane >> 2;
    const int c2 = (lane & 3) * 2;

    const uint32_t a_row  = (uint32_t)(wm * 32 + (lane & 15));
    const uint32_t a_koff = (uint32_t)((lane >> 4) * 8);
    const uint32_t b_row  = (uint32_t)(wn * 16 + (lane & 7) + ((lane >> 4) & 1) * 8);
    const uint32_t b_koff = (uint32_t)(((lane >> 3) & 1) * 8);

    const uint32_t a_base = sb + A_OFF + a_row * APITCH + a_koff * 2;

    float e_acc[4] = {0.f, 0.f, 0.f, 0.f};
    float accH[2][2][4];

    for (int s = 0; s < NSTG; ++s) {
        const int nc = s >> 2;
        const int ks = s & 3;
        const int buf = s & 1;

        if (s + 1 < NSTG) {
            const int nc1 = (s + 1) >> 2;
            const int ks1 = (s + 1) & 3;
            const uint32_t d1 = sb + B_OFF + (uint32_t)(buf ^ 1) * B_STG;
            const size_t gbase = (size_t)nc1 * NCH * 1024 + (size_t)ks1 * 256;
#pragma unroll
            for (int r = 0; r < 4; ++r) {
                int i = tid + r * 256;
                int n = i >> 4, c8 = i & 15;
                const char* srcp = GHB + gbase + (size_t)n * 1024 + (size_t)c8 * 16;
                cp16(d1 + (uint32_t)n * BPITCH + (uint32_t)c8 * 16, srcp);
            }
            CP_COMMIT();
            CP_WAIT(1);
        } else {
            CP_WAIT(0);
        }
        __syncthreads();

        if (ks == 0) {
#pragma unroll
            for (int i = 0; i < 2; ++i)
#pragma unroll
                for (int j = 0; j < 2; ++j)
#pragma unroll
                    for (int r = 0; r < 4; ++r) accH[i][j][r] = 0.f;
        }

        const uint32_t b_hi_base = sb + B_OFF + (uint32_t)buf * B_STG + b_row * BPITCH + b_koff * 2;
        const uint32_t a_kchunk = (uint32_t)(ks * KCH) * 2;

#pragma unroll
        for (int kk = 0; kk < 8; ++kk) {
            const uint32_t kb = (uint32_t)kk * 32;
            uint32_t a0[4], a1[4], bh[4];
            LDSM4(a0[0], a0[1], a0[2], a0[3], a_base + a_kchunk + kb);
            LDSM4(a1[0], a1[1], a1[2], a1[3], a_base + a_kchunk + kb + 16u * APITCH);
            LDSM4(bh[0], bh[1], bh[2], bh[3], b_hi_base + kb);

            MMAH16816(accH[0][0][0], accH[0][0][1], accH[0][0][2], accH[0][0][3],
                      a0[0], a0[1], a0[2], a0[3], bh[0], bh[1]);
            MMAH16816(accH[0][1][0], accH[0][1][1], accH[0][1][2], accH[0][1][3],
                      a0[0], a0[1], a0[2], a0[3], bh[2], bh[3]);
            MMAH16816(accH[1][0][0], accH[1][0][1], accH[1][0][2], accH[1][0][3],
                      a1[0], a1[1], a1[2], a1[3], bh[0], bh[1]);
            MMAH16816(accH[1][1][0], accH[1][1][1], accH[1][1][2], accH[1][1][3],
                      a1[0], a1[1], a1[2], a1[3], bh[2], bh[3]);
        }
        __syncthreads();

        if (ks == 3) {
            // epilogue for this nc: e += V * tanh(accH + t)
#pragma unroll
            for (int mt = 0; mt < 2; ++mt) {
#pragma unroll
                for (int nt = 0; nt < 2; ++nt) {
                    const int n0 = nc * NCH + wn * 16 + nt * 8 + c2;
                    const float t0 = ts[n0], t1 = ts[n0 + 1];
                    const float v0 = vs[n0], v1 = vs[n0 + 1];
#pragma unroll
                    for (int r = 0; r < 4; ++r) {
                        const float tv = (r & 1) ? t1 : t0;
                        const float vv = (r & 1) ? v1 : v0;
                        float x = accH[mt][nt][r] + tv;
                        float ex = __expf(2.0f * x);
                        float th = 1.0f - __fdividef(2.0f, ex + 1.0f);
                        e_acc[mt * 2 + (r >> 1)] = fmaf(vv, th, e_acc[mt * 2 + (r >> 1)]);
                    }
                }
            }
        }
    }

    // reduce e over the 4 lanes sharing a row
#pragma unroll
    for (int j = 0; j < 4; ++j) {
        e_acc[j] += __shfl_xor_sync(0xffffffffu, e_acc[j], 1);
        e_acc[j] += __shfl_xor_sync(0xffffffffu, e_acc[j], 2);
    }
    if ((lane & 3) == 0) {
#pragma unroll
        for (int j = 0; j < 4; ++j) {
            int row = wm * 32 + (j >> 1) * 16 + (j & 1) * 8 + g;
            e_sm[wn * 64 + row] = e_acc[j];
        }
    }
    __syncthreads();
    if (tid < MT) {
        float s = e_sm[tid] + e_sm[64 + tid] + e_sm[128 + tid] + e_sm[192 + tid];
        g_e[m_base + tid] = s;
    }
}

// ---------------- K3: softmax (1024 threads) ----------------
__global__ __launch_bounds__(1024) void softmax_kernel(const float* __restrict__ mask,
                                                       float* __restrict__ out_att) {
    const int b = blockIdx.x;
    const int tid = threadIdx.x;
    const float* e = g_e + (size_t)b * S_;
    __shared__ float red[32];

    float vals[4];
    float mx = -1e30f;
#pragma unroll
    for (int i = 0; i < 4; ++i) {
        vals[i] = e[tid + i * 1024];
        mx = fmaxf(mx, vals[i]);
    }
#pragma unroll
    for (int o = 16; o >= 1; o >>= 1) mx = fmaxf(mx, __shfl_xor_sync(0xffffffffu, mx, o));
    if ((tid & 31) == 0) red[tid >> 5] = mx;
    __syncthreads();
    float M = red[0];
#pragma unroll
    for (int i = 1; i < 32; ++i) M = fmaxf(M, red[i]);
    __syncthreads();

    float sum = 0.0f;
#pragma unroll
    for (int i = 0; i < 4; ++i) {
        vals[i] = expf(vals[i] - M);
        sum += vals[i];
    }
#pragma unroll
    for (int o = 16; o >= 1; o >>= 1) sum += __shfl_xor_sync(0xffffffffu, sum, o);
    if ((tid & 31) == 0) red[tid >> 5] = sum;
    __syncthreads();
    float Ssum = 0.0f;
#pragma unroll
    for (int i = 0; i < 32; ++i) Ssum += red[i];

    const float inv = 1.0f / Ssum;
    const float* mrow = mask + (size_t)b * S_;
    float* orow = out_att + (size_t)b * S_;
#pragma unroll
    for (int i = 0; i < 4; ++i) {
        int s = tid + i * 1024;
        orow[s] = vals[i] * inv * mrow[s];
    }
}

// ---------------- K4: ctx partials (float4 loads, 4-row parallel) ----------
__global__ __launch_bounds__(512) void ctx_partial_kernel(const float* __restrict__ src,
                                                          const float* __restrict__ att) {
    __shared__ float aw[S_PER_SPLIT];
    __shared__ float part[4 * D_];                // 8 KB cross-r reduction buffer
    const int b = blockIdx.x;
    const int sp = blockIdx.y;
    const int tid = threadIdx.x;
    const int r = tid >> 7;                       // 0..3 row-group
    const int c = tid & 127;                      // 0..127 column-quad

    if (tid < S_PER_SPLIT) aw[tid] = att[(size_t)b * S_ + sp * S_PER_SPLIT + tid];
    __syncthreads();

    const float* p = src + ((size_t)b * S_ + (size_t)sp * S_PER_SPLIT + r) * D_ + c * 4;
    float4 acc = make_float4(0.f, 0.f, 0.f, 0.f);
#pragma unroll 4
    for (int s = 0; s < S_PER_SPLIT; s += 4) {
        const float w = aw[s + r];
        const float4 v = *(const float4*)(p + (size_t)s * D_);
        acc.x = fmaf(w, v.x, acc.x);
        acc.y = fmaf(w, v.y, acc.y);
        acc.z = fmaf(w, v.z, acc.z);
        acc.w = fmaf(w, v.w, acc.w);
    }
    *(float4*)(part + r * D_ + c * 4) = acc;
    __syncthreads();

    // reduce 4 row-groups for column d = tid
    const int d = tid;
    float s0 = part[d] + part[D_ + d];
    float s1 = part[2 * D_ + d] + part[3 * D_ + d];
    g_ctx[((size_t)b * SPLIT + sp) * D_ + d] = s0 + s1;
}

// ---------------- K5: reduce + residual ----------------
__global__ __launch_bounds__(512) void reduce_kernel(const float* __restrict__ targ,
                                                     float* __restrict__ out_hidden) {
    const int b = blockIdx.x;
    const int d = threadIdx.x;
    float s = targ[b * D_ + d];
#pragma unroll
    for (int sp = 0; sp < SPLIT; ++sp) s += g_ctx[((size_t)b * SPLIT + sp) * D_ + d];
    out_hidden[b * D_ + d] = s;
}

// ---------------- launcher ----------------
extern "C" void kernel_launch(void* const* d_in, const int* in_sizes, int n_in,
                              void* d_out, int out_size) {
    const float* targ = (const float*)d_in[0];
    const float* src  = (const float*)d_in[1];
    const float* mask = (const float*)d_in[2];
    const float* W    = (const float*)d_in[3];
    const float* V    = (const float*)d_in[4];

    float* out = (float*)d_out;
    float* out_att    = out;
    float* out_hidden = out + B_ * S_;

    cudaFuncSetAttribute(gemm_e_mma, cudaFuncAttributeMaxDynamicSharedMemorySize, SMEM_TOTAL);

    wsplit_kernel<<<H_ * D_ / 256, 256>>>(W);
    t_kernel<<<B_, D_>>>(targ, W);
    gemm_e_mma<<<M_ / MT, 256, SMEM_TOTAL>>>(src, V);
    softmax_kernel<<<B_, 1024>>>(mask, out_att);
    dim3 g4(B_, SPLIT);
    ctx_partial_kernel<<<g4, D_>>>(src, out_att);
    reduce_kernel<<<B_, D_>>>(targ, out_hidden);
}